// round 12
// baseline (speedup 1.0000x reference)
#include <cuda_runtime.h>

// RALoss fused: loss = sum_i mean_j 10*exp(-sum_{hw}(amax[i,j,hw]-aorg[i,j,hw]))
// Shapes: (4, 64, 512, 512) fp32 x2, scalar fp32 out.
// Input-split streaming: each block streams ONE contiguous 512KB chunk of ONE
// input (pure unidirectional stream; no amax/aorg interleaving per warp).
// Per-pair: 2 amax-blocks (+) and 2 aorg-blocks (-); finalize sums 4 signed
// partials in fixed order (deterministic). 1024 blocks = single wave.

#define L_DIM 4
#define B_DIM 64
#define PAIRS (L_DIM * B_DIM)        // 256
#define HW (512 * 512)               // 262144 elems per (i,j) map
#define PAIR_F4 (HW / 4)             // 65536 float4 per pair
#define HALF_F4 (PAIR_F4 / 2)        // 32768 float4 per half
#define THREADS 256
#define ITERS 32                     // per iter: 256 thr * 4 f4 = 1024 f4; 32*1024=32768
#define SLOTS 4                      // partial slots per pair
#define GRID_TOTAL (PAIRS * SLOTS)   // 1024 blocks

__device__ float g_partials[GRID_TOTAL];
__device__ unsigned int g_done_count;   // zero-init at load; reset each replay

// 128-bit non-coherent load, 256B L2 fetch granularity.
__device__ __forceinline__ float4 ldg_nc_256(const float4* p) {
    float4 v;
    asm("ld.global.nc.L2::256B.v4.f32 {%0,%1,%2,%3}, [%4];"
        : "=f"(v.x), "=f"(v.y), "=f"(v.z), "=f"(v.w)
        : "l"(p));
    return v;
}

__global__ __launch_bounds__(THREADS, 7)
void raloss_fused_kernel(const float4* __restrict__ amax,
                         const float4* __restrict__ aorg,
                         float* __restrict__ out) {
    const unsigned int slot = blockIdx.x;   // 0,1: amax halves; 2,3: aorg halves
    const unsigned int pair = blockIdx.y;   // 0..255
    const unsigned int tid  = threadIdx.x;
    const unsigned int warp = tid >> 5;
    const unsigned int lane = tid & 31;

    const unsigned int is_org = slot >> 1;
    const unsigned int half   = slot & 1u;

    const float4* src = is_org ? aorg : amax;
    const float4* p = src + pair * PAIR_F4 + half * HALF_F4 + tid;

    float acc0 = 0.0f, acc1 = 0.0f, acc2 = 0.0f, acc3 = 0.0f;

#pragma unroll
    for (int it = 0; it < ITERS; it++) {
        // 4 front-batched independent 128-bit loads from ONE stream.
        float4 v0 = ldg_nc_256(p + 0 * THREADS);
        float4 v1 = ldg_nc_256(p + 1 * THREADS);
        float4 v2 = ldg_nc_256(p + 2 * THREADS);
        float4 v3 = ldg_nc_256(p + 3 * THREADS);

        acc0 += (v0.x + v0.y) + (v0.z + v0.w);
        acc1 += (v1.x + v1.y) + (v1.z + v1.w);
        acc2 += (v2.x + v2.y) + (v2.z + v2.w);
        acc3 += (v3.x + v3.y) + (v3.z + v3.w);

        p += 4 * THREADS;
    }

    float s = (acc0 + acc1) + (acc2 + acc3);

#pragma unroll
    for (int off = 16; off > 0; off >>= 1)
        s += __shfl_xor_sync(0xFFFFFFFFu, s, off);

    __shared__ float warp_sums[THREADS / 32];
    __shared__ bool  s_is_last;
    if (lane == 0) warp_sums[warp] = s;
    __syncthreads();

    if (warp == 0) {
        float v = (lane < (THREADS / 32)) ? warp_sums[lane] : 0.0f;
#pragma unroll
        for (int off = 4; off > 0; off >>= 1)
            v += __shfl_xor_sync(0xFFFFFFFFu, v, off);
        if (lane == 0) {
            // aorg partials stored negated: pair diff = sum of 4 slot partials.
            g_partials[pair * SLOTS + slot] = is_org ? -v : v;
            unsigned int old;
            asm volatile("atom.acq_rel.gpu.global.add.u32 %0, [%1], %2;"
                         : "=r"(old)
                         : "l"(&g_done_count), "r"(1u)
                         : "memory");
            s_is_last = (old == (unsigned int)(GRID_TOTAL - 1));
        }
    }
    __syncthreads();

    // ---- Last block finalizes: 1024 partials, L2-resident ----
    if (s_is_last) {
        // Thread t owns pair t: fixed-order sum of its 4 signed partials.
        float d = 0.0f;
#pragma unroll
        for (int k = 0; k < SLOTS; k++)
            d += __ldcg(&g_partials[tid * SLOTS + k]);

        // contribution: 10*exp(-d)/64  (sum_i mean_j == sum over 256 pairs / 64)
        float v = 10.0f * expf(-d) * (1.0f / (float)B_DIM);

#pragma unroll
        for (int off = 16; off > 0; off >>= 1)
            v += __shfl_xor_sync(0xFFFFFFFFu, v, off);

        if (lane == 0) warp_sums[warp] = v;
        __syncthreads();

        if (warp == 0) {
            float w = (lane < (THREADS / 32)) ? warp_sums[lane] : 0.0f;
#pragma unroll
            for (int off = 4; off > 0; off >>= 1)
                w += __shfl_xor_sync(0xFFFFFFFFu, w, off);
            if (lane == 0) {
                out[0] = w;
                g_done_count = 0;   // reset for next graph replay
            }
        }
    }
}

extern "C" void kernel_launch(void* const* d_in, const int* in_sizes, int n_in,
                              void* d_out, int out_size) {
    const float4* amax = (const float4*)d_in[0];
    const float4* aorg = (const float4*)d_in[1];
    float* out = (float*)d_out;

    dim3 grid(SLOTS, PAIRS, 1);
    raloss_fused_kernel<<<grid, THREADS>>>(amax, aorg, out);
}

// round 13
// speedup vs baseline: 1.0020x; 1.0020x over previous
#include <cuda_runtime.h>

// RALoss fused: loss = sum_i mean_j 10*exp(-sum_{hw}(amax[i,j,hw]-aorg[i,j,hw]))
// Shapes: (4, 64, 512, 512) fp32 x2, scalar fp32 out.
// Champion streaming (1024 pair-aligned blocks, 8 batched LDG.128 L2::256B)
// + hierarchical early finalize: 4th block of each pair computes that pair's
// exp DURING streaming; 256th pair-finisher does only a 256->1 reduce.
// All reduction orders fixed -> deterministic independent of arrival order.

#define L_DIM 4
#define B_DIM 64
#define PAIRS (L_DIM * B_DIM)        // 256
#define HW (512 * 512)               // 262144 elems per (i,j) map
#define PAIR_F4 (HW / 4)             // 65536 float4 per pair
#define BLKS_PER_PAIR 4
#define THREADS 256
#define ITERS 16                     // per iter: 256 thr * 4 f4 = 1024 f4
#define GRID_TOTAL (PAIRS * BLKS_PER_PAIR)   // 1024 blocks

__device__ float g_partials[GRID_TOTAL];
__device__ float g_pair_loss[PAIRS];
__device__ unsigned int g_pair_count[PAIRS];   // zero-init; reset each replay
__device__ unsigned int g_final_count;         // zero-init; reset each replay

// 128-bit non-coherent load, 256B L2 fetch granularity.
__device__ __forceinline__ float4 ldg_nc_256(const float4* p) {
    float4 v;
    asm("ld.global.nc.L2::256B.v4.f32 {%0,%1,%2,%3}, [%4];"
        : "=f"(v.x), "=f"(v.y), "=f"(v.z), "=f"(v.w)
        : "l"(p));
    return v;
}

__device__ __forceinline__ unsigned int atom_acq_rel_inc(unsigned int* ctr) {
    unsigned int old;
    asm volatile("atom.acq_rel.gpu.global.add.u32 %0, [%1], %2;"
                 : "=r"(old) : "l"(ctr), "r"(1u) : "memory");
    return old;
}

__global__ __launch_bounds__(THREADS, 7)
void raloss_fused_kernel(const float4* __restrict__ amax,
                         const float4* __restrict__ aorg,
                         float* __restrict__ out) {
    const unsigned int blk  = blockIdx.x;   // 0..3   (chunk within pair)
    const unsigned int pair = blockIdx.y;   // 0..255
    const unsigned int tid  = threadIdx.x;
    const unsigned int warp = tid >> 5;
    const unsigned int lane = tid & 31;

    const unsigned int base = pair * PAIR_F4 + blk * (ITERS * THREADS * 4);
    const float4* pa = amax + base + tid;
    const float4* po = aorg + base + tid;

    float acc0 = 0.0f, acc1 = 0.0f, acc2 = 0.0f, acc3 = 0.0f;

#pragma unroll
    for (int it = 0; it < ITERS; it++) {
        float4 ma0 = ldg_nc_256(pa + 0 * THREADS);
        float4 ma1 = ldg_nc_256(pa + 1 * THREADS);
        float4 ma2 = ldg_nc_256(pa + 2 * THREADS);
        float4 ma3 = ldg_nc_256(pa + 3 * THREADS);
        float4 mo0 = ldg_nc_256(po + 0 * THREADS);
        float4 mo1 = ldg_nc_256(po + 1 * THREADS);
        float4 mo2 = ldg_nc_256(po + 2 * THREADS);
        float4 mo3 = ldg_nc_256(po + 3 * THREADS);

        acc0 += (ma0.x - mo0.x) + (ma0.y - mo0.y) + (ma0.z - mo0.z) + (ma0.w - mo0.w);
        acc1 += (ma1.x - mo1.x) + (ma1.y - mo1.y) + (ma1.z - mo1.z) + (ma1.w - mo1.w);
        acc2 += (ma2.x - mo2.x) + (ma2.y - mo2.y) + (ma2.z - mo2.z) + (ma2.w - mo2.w);
        acc3 += (ma3.x - mo3.x) + (ma3.y - mo3.y) + (ma3.z - mo3.z) + (ma3.w - mo3.w);

        pa += 4 * THREADS;
        po += 4 * THREADS;
    }

    float s = (acc0 + acc1) + (acc2 + acc3);

#pragma unroll
    for (int off = 16; off > 0; off >>= 1)
        s += __shfl_xor_sync(0xFFFFFFFFu, s, off);

    __shared__ float warp_sums[THREADS / 32];
    __shared__ bool  s_is_final;
    if (lane == 0) warp_sums[warp] = s;
    __syncthreads();

    if (warp == 0) {
        float v = (lane < (THREADS / 32)) ? warp_sums[lane] : 0.0f;
#pragma unroll
        for (int off = 4; off > 0; off >>= 1)
            v += __shfl_xor_sync(0xFFFFFFFFu, v, off);

        if (lane == 0) {
            bool final_blk = false;
            g_partials[pair * BLKS_PER_PAIR + blk] = v;
            // Release partial + count arrivals for this pair.
            unsigned int old = atom_acq_rel_inc(&g_pair_count[pair]);
            if (old == BLKS_PER_PAIR - 1) {
                // 4th arriver finalizes this pair NOW (overlaps other pairs'
                // streaming). Fixed-order sum -> deterministic.
                float d = 0.0f;
#pragma unroll
                for (int k = 0; k < BLKS_PER_PAIR; k++)
                    d += __ldcg(&g_partials[pair * BLKS_PER_PAIR + k]);
                g_pair_loss[pair] = 10.0f * expf(-d) * (1.0f / (float)B_DIM);
                // Release pair loss + count finished pairs.
                unsigned int old2 = atom_acq_rel_inc(&g_final_count);
                final_blk = (old2 == (unsigned int)(PAIRS - 1));
            }
            s_is_final = final_blk;
        }
    }
    __syncthreads();

    // ---- Final block: only a 256 -> 1 reduce (everything else already done) ----
    if (s_is_final) {
        float v = __ldcg(&g_pair_loss[tid]);   // thread t owns pair t

#pragma unroll
        for (int off = 16; off > 0; off >>= 1)
            v += __shfl_xor_sync(0xFFFFFFFFu, v, off);

        if (lane == 0) warp_sums[warp] = v;
        __syncthreads();

        if (warp == 0) {
            float w = (lane < (THREADS / 32)) ? warp_sums[lane] : 0.0f;
#pragma unroll
            for (int off = 4; off > 0; off >>= 1)
                w += __shfl_xor_sync(0xFFFFFFFFu, w, off);
            if (lane == 0)
                out[0] = w;
        }

        // Reset counters for next graph replay (all pairs complete here).
        g_pair_count[tid] = 0;
        if (tid == 0) g_final_count = 0;
    }
}

extern "C" void kernel_launch(void* const* d_in, const int* in_sizes, int n_in,
                              void* d_out, int out_size) {
    const float4* amax = (const float4*)d_in[0];
    const float4* aorg = (const float4*)d_in[1];
    float* out = (float*)d_out;

    dim3 grid(BLKS_PER_PAIR, PAIRS, 1);
    raloss_fused_kernel<<<grid, THREADS>>>(amax, aorg, out);
}

// round 14
// speedup vs baseline: 1.0163x; 1.0143x over previous
#include <cuda_runtime.h>

// RALoss fused: loss = sum_i mean_j 10*exp(-sum_{hw}(amax[i,j,hw]-aorg[i,j,hw]))
// Shapes: (4, 64, 512, 512) fp32 x2, scalar fp32 out.
// CHAMPION (convergence re-bench): 1024 pair-aligned blocks, single wave,
// 8 front-batched LDG.128 with 256B L2 granularity, acq_rel last-block
// finalize, fixed-order sums -> deterministic.

#define L_DIM 4
#define B_DIM 64
#define PAIRS (L_DIM * B_DIM)        // 256
#define HW (512 * 512)               // 262144 elems per (i,j) map
#define PAIR_F4 (HW / 4)             // 65536 float4 per pair
#define BLKS_PER_PAIR 4
#define THREADS 256
#define ITERS 16                     // per iter: 256 thr * 4 f4 = 1024 f4
#define GRID_TOTAL (PAIRS * BLKS_PER_PAIR)   // 1024 blocks

__device__ float g_partials[GRID_TOTAL];
__device__ unsigned int g_done_count;   // zero-init at load; reset each replay

// 128-bit non-coherent load, 256B L2 fetch granularity.
__device__ __forceinline__ float4 ldg_nc_256(const float4* p) {
    float4 v;
    asm("ld.global.nc.L2::256B.v4.f32 {%0,%1,%2,%3}, [%4];"
        : "=f"(v.x), "=f"(v.y), "=f"(v.z), "=f"(v.w)
        : "l"(p));
    return v;
}

__global__ __launch_bounds__(THREADS, 7)
void raloss_fused_kernel(const float4* __restrict__ amax,
                         const float4* __restrict__ aorg,
                         float* __restrict__ out) {
    const unsigned int blk  = blockIdx.x;   // 0..3   (chunk within pair)
    const unsigned int pair = blockIdx.y;   // 0..255
    const unsigned int tid  = threadIdx.x;
    const unsigned int warp = tid >> 5;
    const unsigned int lane = tid & 31;

    const unsigned int base = pair * PAIR_F4 + blk * (ITERS * THREADS * 4);
    const float4* pa = amax + base + tid;
    const float4* po = aorg + base + tid;

    float acc0 = 0.0f, acc1 = 0.0f, acc2 = 0.0f, acc3 = 0.0f;

#pragma unroll
    for (int it = 0; it < ITERS; it++) {
        float4 ma0 = ldg_nc_256(pa + 0 * THREADS);
        float4 ma1 = ldg_nc_256(pa + 1 * THREADS);
        float4 ma2 = ldg_nc_256(pa + 2 * THREADS);
        float4 ma3 = ldg_nc_256(pa + 3 * THREADS);
        float4 mo0 = ldg_nc_256(po + 0 * THREADS);
        float4 mo1 = ldg_nc_256(po + 1 * THREADS);
        float4 mo2 = ldg_nc_256(po + 2 * THREADS);
        float4 mo3 = ldg_nc_256(po + 3 * THREADS);

        acc0 += (ma0.x - mo0.x) + (ma0.y - mo0.y) + (ma0.z - mo0.z) + (ma0.w - mo0.w);
        acc1 += (ma1.x - mo1.x) + (ma1.y - mo1.y) + (ma1.z - mo1.z) + (ma1.w - mo1.w);
        acc2 += (ma2.x - mo2.x) + (ma2.y - mo2.y) + (ma2.z - mo2.z) + (ma2.w - mo2.w);
        acc3 += (ma3.x - mo3.x) + (ma3.y - mo3.y) + (ma3.z - mo3.z) + (ma3.w - mo3.w);

        pa += 4 * THREADS;
        po += 4 * THREADS;
    }

    float s = (acc0 + acc1) + (acc2 + acc3);

#pragma unroll
    for (int off = 16; off > 0; off >>= 1)
        s += __shfl_xor_sync(0xFFFFFFFFu, s, off);

    __shared__ float warp_sums[THREADS / 32];
    __shared__ bool  s_is_last;
    if (lane == 0) warp_sums[warp] = s;
    __syncthreads();

    if (warp == 0) {
        float v = (lane < (THREADS / 32)) ? warp_sums[lane] : 0.0f;
#pragma unroll
        for (int off = 4; off > 0; off >>= 1)
            v += __shfl_xor_sync(0xFFFFFFFFu, v, off);
        if (lane == 0) {
            g_partials[pair * BLKS_PER_PAIR + blk] = v;
            // Release publishes the partial; winner's acquire sees all partials.
            unsigned int old;
            asm volatile("atom.acq_rel.gpu.global.add.u32 %0, [%1], %2;"
                         : "=r"(old)
                         : "l"(&g_done_count), "r"(1u)
                         : "memory");
            s_is_last = (old == (unsigned int)(GRID_TOTAL - 1));
        }
    }
    __syncthreads();

    // ---- Last block finalizes: 1024 partials, L2-resident ----
    if (s_is_last) {
        // Thread t owns pair t: fixed-order sum of its 4 partials (deterministic).
        float d = 0.0f;
#pragma unroll
        for (int k = 0; k < BLKS_PER_PAIR; k++)
            d += __ldcg(&g_partials[tid * BLKS_PER_PAIR + k]);

        // contribution: 10*exp(-d)/64  (sum_i mean_j == sum over 256 pairs / 64)
        float v = 10.0f * expf(-d) * (1.0f / (float)B_DIM);

#pragma unroll
        for (int off = 16; off > 0; off >>= 1)
            v += __shfl_xor_sync(0xFFFFFFFFu, v, off);

        if (lane == 0) warp_sums[warp] = v;
        __syncthreads();

        if (warp == 0) {
            float w = (lane < (THREADS / 32)) ? warp_sums[lane] : 0.0f;
#pragma unroll
            for (int off = 4; off > 0; off >>= 1)
                w += __shfl_xor_sync(0xFFFFFFFFu, w, off);
            if (lane == 0) {
                out[0] = w;
                g_done_count = 0;   // reset for next graph replay
            }
        }
    }
}

extern "C" void kernel_launch(void* const* d_in, const int* in_sizes, int n_in,
                              void* d_out, int out_size) {
    const float4* amax = (const float4*)d_in[0];
    const float4* aorg = (const float4*)d_in[1];
    float* out = (float*)d_out;

    dim3 grid(BLKS_PER_PAIR, PAIRS, 1);
    raloss_fused_kernel<<<grid, THREADS>>>(amax, aorg, out);
}